// round 6
// baseline (speedup 1.0000x reference)
#include <cuda_runtime.h>
#include <cuda_fp16.h>
#include <math.h>
#include <stdint.h>

// ---------------------------------------------------------------------------
// Problem constants
// ---------------------------------------------------------------------------
#define BATCH 2
#define SEQ   2048
#define EMB   1024
#define HEADS 16
#define HDIM  64
#define MROWS 4096
#define E3    3072

// fp16 hi/lo scratch (no cudaMalloc allowed)
__device__ __half g_xh[MROWS * EMB],  g_xl[MROWS * EMB];
__device__ __half g_wih[E3 * EMB],    g_wil[E3 * EMB];
__device__ __half g_woh[EMB * EMB],   g_wol[EMB * EMB];
__device__ __half g_qkvh[(size_t)MROWS * E3], g_qkvl[(size_t)MROWS * E3];
__device__ __half g_ctxh[MROWS * EMB], g_ctxl[MROWS * EMB];

// ---------------------------------------------------------------------------
// PTX helpers (sm_80+ only — legal under compute_103)
// ---------------------------------------------------------------------------
__device__ __forceinline__ uint32_t smem_u32(const void* p) {
    uint32_t a;
    asm("{ .reg .u64 t; cvta.to.shared.u64 t, %1; cvt.u32.u64 %0, t; }"
        : "=r"(a) : "l"(p));
    return a;
}

__device__ __forceinline__ void ldsm4(uint32_t r[4], uint32_t addr) {
    asm volatile("ldmatrix.sync.aligned.m8n8.x4.shared.b16 {%0,%1,%2,%3}, [%4];"
                 : "=r"(r[0]), "=r"(r[1]), "=r"(r[2]), "=r"(r[3]) : "r"(addr));
}
__device__ __forceinline__ void ldsm4t(uint32_t r[4], uint32_t addr) {
    asm volatile("ldmatrix.sync.aligned.m8n8.x4.trans.shared.b16 {%0,%1,%2,%3}, [%4];"
                 : "=r"(r[0]), "=r"(r[1]), "=r"(r[2]), "=r"(r[3]) : "r"(addr));
}
__device__ __forceinline__ void ldsm2(uint32_t r[2], uint32_t addr) {
    asm volatile("ldmatrix.sync.aligned.m8n8.x2.shared.b16 {%0,%1}, [%2];"
                 : "=r"(r[0]), "=r"(r[1]) : "r"(addr));
}
__device__ __forceinline__ void mma16816(float d[4], const uint32_t a[4], const uint32_t b[2]) {
    asm volatile(
        "mma.sync.aligned.m16n8k16.row.col.f32.f16.f16.f32 "
        "{%0,%1,%2,%3}, {%4,%5,%6,%7}, {%8,%9}, {%0,%1,%2,%3};"
        : "+f"(d[0]), "+f"(d[1]), "+f"(d[2]), "+f"(d[3])
        : "r"(a[0]), "r"(a[1]), "r"(a[2]), "r"(a[3]), "r"(b[0]), "r"(b[1]));
}
__device__ __forceinline__ float ex2f(float x) {
    float y;
    asm("ex2.approx.f32 %0, %1;" : "=f"(y) : "f"(x));
    return y;
}

#define CP16(dst, src) \
    asm volatile("cp.async.cg.shared.global [%0], [%1], 16;" :: "r"(dst), "l"(src))
#define CP_COMMIT() asm volatile("cp.async.commit_group;")
#define CP_WAIT(n)  asm volatile("cp.async.wait_group %0;" :: "n"(n))

__device__ __forceinline__ void split_pack_h(float a, float b, uint32_t& h, uint32_t& l) {
    __half2 hh = __float22half2_rn(make_float2(a, b));
    float2 f = __half22float2(hh);
    __half2 ll = __float22half2_rn(make_float2(a - f.x, b - f.y));
    h = *(uint32_t*)&hh;
    l = *(uint32_t*)&ll;
}

// ---------------------------------------------------------------------------
// fp32 -> fp16 hi/lo conversion (elementwise, vectorized by 4)
// ---------------------------------------------------------------------------
__global__ void cvt_hl_kernel(const float* __restrict__ src,
                              __half* __restrict__ h, __half* __restrict__ l, int n4)
{
    int i = blockIdx.x * blockDim.x + threadIdx.x;
    if (i >= n4) return;
    float4 v = ((const float4*)src)[i];
    uint32_t h01, l01, h23, l23;
    split_pack_h(v.x, v.y, h01, l01);
    split_pack_h(v.z, v.w, h23, l23);
    ((uint32_t*)h)[i * 2]     = h01;
    ((uint32_t*)h)[i * 2 + 1] = h23;
    ((uint32_t*)l)[i * 2]     = l01;
    ((uint32_t*)l)[i * 2 + 1] = l23;
}

// ---------------------------------------------------------------------------
// GEMM NT (fp16 hi/lo preconverted, 3-term, fp32 accumulate):
//   C[M,N] = A[M,K] @ B[N,K]^T + bias[N]
// 128x128 tile, 8 warps (64x32), K-chunk 16, 4-stage cp.async pipeline.
// If Cf != null: write fp32. Else write fp16 hi/lo (Ch/Cl).
// ---------------------------------------------------------------------------
#define GP      24                  // pitch (elems): 16 data + 8 pad (48B, 16B mult)
#define GSTG_E  (128 * GP)          // 3072 elems per buffer
#define GSTGB   (4 * GSTG_E * 2)    // Ah,Al,Bh,Bl = 24576 B per stage
#define GNSTAGE 4
#define GEMM_SMEM (GNSTAGE * GSTGB) // 98304 B

__global__ void __launch_bounds__(256, 1)
gemm_fp16hl(const __half* __restrict__ Ah, const __half* __restrict__ Al,
            const __half* __restrict__ Bh, const __half* __restrict__ Bl,
            const float* __restrict__ bias,
            float* __restrict__ Cf, __half* __restrict__ Ch, __half* __restrict__ Cl,
            int M, int N, int K)
{
    extern __shared__ __half smem[];
    const uint32_t sb = smem_u32(smem);

    const int tid  = threadIdx.x;
    const int lane = tid & 31;
    const int warp = tid >> 5;
    const int wm   = warp & 1;
    const int wn   = warp >> 1;
    const int m0   = blockIdx.y * 128;
    const int n0   = blockIdx.x * 128;

    // cp.async geometry: thread -> (row, 8-elem segment)
    const int crow = tid >> 1;
    const int cseg = (tid & 1) * 8;
    const __half* apH = Ah + (size_t)(m0 + crow) * K + cseg;
    const __half* apL = Al + (size_t)(m0 + crow) * K + cseg;
    const __half* bpH = Bh + (size_t)(n0 + crow) * K + cseg;
    const __half* bpL = Bl + (size_t)(n0 + crow) * K + cseg;
    const uint32_t dstoff = (uint32_t)(crow * GP + cseg) * 2;

    auto issue = [&](int c) {
        uint32_t base = sb + (uint32_t)(c & (GNSTAGE - 1)) * GSTGB + dstoff;
        int go = c * 16;
        CP16(base,                  apH + go);
        CP16(base + GSTG_E * 2,     apL + go);
        CP16(base + 2 * GSTG_E * 2, bpH + go);
        CP16(base + 3 * GSTG_E * 2, bpL + go);
    };

    const int nch = K / 16;
#pragma unroll
    for (int c = 0; c < 3; c++) {
        issue(c);
        CP_COMMIT();
    }

    float acc[4][4][4];
#pragma unroll
    for (int mi = 0; mi < 4; mi++)
#pragma unroll
        for (int ni = 0; ni < 4; ni++)
#pragma unroll
            for (int f = 0; f < 4; f++) acc[mi][ni][f] = 0.0f;

    const int arow  = lane & 15;
    const int acolb = (lane >> 4) * 8;
    const int brow  = lane & 7;
    const int bcolb = ((lane >> 3) & 1) * 8;

#pragma unroll 1
    for (int c = 0; c < nch; c++) {
        CP_WAIT(2);
        __syncthreads();
        if (c + 3 < nch) issue(c + 3);
        CP_COMMIT();

        const uint32_t stg = sb + (uint32_t)(c & (GNSTAGE - 1)) * GSTGB;
        uint32_t ah[4][4], al[4][4];
#pragma unroll
        for (int mi = 0; mi < 4; mi++) {
            uint32_t ad = stg + ((wm * 64 + mi * 16 + arow) * GP + acolb) * 2;
            ldsm4(ah[mi], ad);
            ldsm4(al[mi], ad + GSTG_E * 2);
        }
#pragma unroll
        for (int ni = 0; ni < 4; ni++) {
            uint32_t bd = stg + 2 * GSTG_E * 2 + ((wn * 32 + ni * 8 + brow) * GP + bcolb) * 2;
            uint32_t bh[2], bl[2];
            ldsm2(bh, bd);
            ldsm2(bl, bd + GSTG_E * 2);
#pragma unroll
            for (int mi = 0; mi < 4; mi++) {
                mma16816(acc[mi][ni], ah[mi], bh);
                mma16816(acc[mi][ni], ah[mi], bl);
                mma16816(acc[mi][ni], al[mi], bh);
            }
        }
    }

    // epilogue
    const int erow = lane >> 2;
    const int ecol = (lane & 3) * 2;
#pragma unroll
    for (int mi = 0; mi < 4; mi++) {
        int r0 = m0 + wm * 64 + mi * 16 + erow;
#pragma unroll
        for (int ni = 0; ni < 4; ni++) {
            int cc = n0 + wn * 32 + ni * 8 + ecol;
            float b0 = bias[cc], b1 = bias[cc + 1];
            float x0 = acc[mi][ni][0] + b0, x1 = acc[mi][ni][1] + b1;
            float x2 = acc[mi][ni][2] + b0, x3 = acc[mi][ni][3] + b1;
            if (Cf) {
                *(float2*)(Cf + (size_t)r0 * N + cc)       = make_float2(x0, x1);
                *(float2*)(Cf + (size_t)(r0 + 8) * N + cc) = make_float2(x2, x3);
            } else {
                uint32_t hh, ll;
                split_pack_h(x0, x1, hh, ll);
                ((uint32_t*)Ch)[((size_t)r0 * N + cc) >> 1] = hh;
                ((uint32_t*)Cl)[((size_t)r0 * N + cc) >> 1] = ll;
                split_pack_h(x2, x3, hh, ll);
                ((uint32_t*)Ch)[((size_t)(r0 + 8) * N + cc) >> 1] = hh;
                ((uint32_t*)Cl)[((size_t)(r0 + 8) * N + cc) >> 1] = ll;
            }
        }
    }
}

// ---------------------------------------------------------------------------
// Flash attention, fp16 hi/lo operands via cp.async. CTA = 128 q x one (b,h).
// 8 warps x 16 q-rows. KV tiles of 64, 2-stage cp.async. Softmax log2 domain.
// Reads qkv hi/lo fp16, writes ctx hi/lo fp16.
// ---------------------------------------------------------------------------
#define AP      72                  // pitch: 64 data + 8 pad (144B, 16B mult)
#define AKV_E   (64 * AP)           // 4608 elems per buffer
#define ASTGB   (4 * AKV_E * 2)     // Kh,Kl,Vh,Vl = 36864 B per stage
#define ATT_SMEM (2 * ASTGB)        // 73728 B  (Q staged through stage0 region)

#define QK_SCALE 0.18033688011112042f   // 0.125 * log2(e)
#define MASK_C   (-14426.950408889634f) // -10000 * log2(e)

__global__ void __launch_bounds__(256, 1)
attn_fp16(const __half* __restrict__ qkvh, const __half* __restrict__ qkvl,
          const float* __restrict__ mask,
          __half* __restrict__ ctxh, __half* __restrict__ ctxl)
{
    extern __shared__ __half smem[];
    const uint32_t sb = smem_u32(smem);

    const int tid  = threadIdx.x;
    const int lane = tid & 31;
    const int warp = tid >> 5;
    const int qt = blockIdx.x;
    const int h  = blockIdx.y;
    const int b  = blockIdx.z;
    const int q0 = qt * 128;

    const size_t rowbase = (size_t)b * SEQ;
    const __half* qbH = qkvh + rowbase * E3 + h * HDIM;
    const __half* qbL = qkvl + rowbase * E3 + h * HDIM;
    const __half* kbH = qbH + EMB;
    const __half* kbL = qbL + EMB;
    const __half* vbH = qbH + 2 * EMB;
    const __half* vbL = qbL + 2 * EMB;

    // ---- load Q (hi/lo) via cp.async into stage0 region ----
#pragma unroll
    for (int i = 0; i < 4; i++) {
        int idx = tid + i * 256;              // 0..1023
        int row = idx >> 3;                   // 0..127
        int sg  = (idx & 7) * 8;              // 0..56
        uint32_t dst = sb + (uint32_t)(row * AP + sg) * 2;
        CP16(dst, qbH + (size_t)(q0 + row) * E3 + sg);
        CP16(dst + 128 * AP * 2, qbL + (size_t)(q0 + row) * E3 + sg);
    }
    CP_COMMIT();
    CP_WAIT(0);
    __syncthreads();

    // ---- Q fragments to registers ----
    uint32_t qh[4][4], ql[4][4];
    {
        const int arow  = warp * 16 + (lane & 15);
        const int acolb = (lane >> 4) * 8;
#pragma unroll
        for (int ks = 0; ks < 4; ks++) {
            uint32_t ad = sb + (uint32_t)(arow * AP + ks * 16 + acolb) * 2;
            ldsm4(qh[ks], ad);
            ldsm4(ql[ks], ad + 128 * AP * 2);
        }
    }
    __syncthreads();   // all warps done reading Q region before KV overwrites

    // ---- KV cp.async geometry ----
    int kvr[2], kvs[2];
    uint32_t kvd[2];
#pragma unroll
    for (int j = 0; j < 2; j++) {
        int idx = tid + j * 256;              // 0..511
        kvr[j] = idx >> 3;                    // 0..63
        kvs[j] = (idx & 7) * 8;
        kvd[j] = (uint32_t)(kvr[j] * AP + kvs[j]) * 2;
    }

    auto issueKV = [&](int c) {
        uint32_t base = sb + (uint32_t)(c & 1) * ASTGB;
        size_t kv0 = (size_t)c * 64;
#pragma unroll
        for (int j = 0; j < 2; j++) {
            size_t go = (kv0 + kvr[j]) * E3 + kvs[j];
            uint32_t d = base + kvd[j];
            CP16(d,                 kbH + go);
            CP16(d + AKV_E * 2,     kbL + go);
            CP16(d + 2 * AKV_E * 2, vbH + go);
            CP16(d + 3 * AKV_E * 2, vbL + go);
        }
    };

    issueKV(0); CP_COMMIT();
    issueKV(1); CP_COMMIT();

    // ---- state ----
    float o[8][4];
#pragma unroll
    for (int nt = 0; nt < 8; nt++)
#pragma unroll
        for (int f = 0; f < 4; f++) o[nt][f] = 0.0f;
    float m0r = -INFINITY, m1r = -INFINITY;
    float l0r = 0.0f, l1r = 0.0f;

    const int kfrow = ((lane >> 4) & 1) * 8 + (lane & 7);
    const int kfcol = ((lane >> 3) & 1) * 8;
    const int vfrow = ((lane >> 3) & 1) * 8 + (lane & 7);
    const int vfcol = ((lane >> 4) & 1) * 8;
    const float* mrow0 = mask + ((size_t)b * SEQ + q0 + warp * 16 + (lane >> 2)) * SEQ
                         + (lane & 3) * 2;
    const float* mrow1 = mrow0 + 8 * SEQ;

    const int NKV = SEQ / 64;                 // 32
#pragma unroll 1
    for (int c = 0; c < NKV; c++) {
        CP_WAIT(1);
        __syncthreads();
        const uint32_t stg = sb + (uint32_t)(c & 1) * ASTGB;

        // ---- S = Q @ K^T (hi/lo 3-term) ----
        float s[8][4];
#pragma unroll
        for (int nt = 0; nt < 8; nt++)
#pragma unroll
            for (int f = 0; f < 4; f++) s[nt][f] = 0.0f;

#pragma unroll
        for (int ks = 0; ks < 4; ks++) {
#pragma unroll
            for (int nt2 = 0; nt2 < 4; nt2++) {
                uint32_t ka = stg + (uint32_t)((nt2 * 16 + kfrow) * AP + ks * 16 + kfcol) * 2;
                uint32_t kh4[4], kl4[4];
                ldsm4(kh4, ka);
                ldsm4(kl4, ka + AKV_E * 2);
                mma16816(s[2 * nt2],     qh[ks], kh4);
                mma16816(s[2 * nt2],     qh[ks], kl4);
                mma16816(s[2 * nt2],     ql[ks], kh4);
                mma16816(s[2 * nt2 + 1], qh[ks], kh4 + 2);
                mma16816(s[2 * nt2 + 1], qh[ks], kl4 + 2);
                mma16816(s[2 * nt2 + 1], ql[ks], kh4 + 2);
            }
        }

        // ---- scale + mask (log2 domain) ----
        const int kvb = c * 64;
#pragma unroll
        for (int nt = 0; nt < 8; nt++) {
            float2 mv0 = *(const float2*)(mrow0 + kvb + nt * 8);
            float2 mv1 = *(const float2*)(mrow1 + kvb + nt * 8);
            s[nt][0] = fmaf(mv0.x, MASK_C, s[nt][0] * QK_SCALE);
            s[nt][1] = fmaf(mv0.y, MASK_C, s[nt][1] * QK_SCALE);
            s[nt][2] = fmaf(mv1.x, MASK_C, s[nt][2] * QK_SCALE);
            s[nt][3] = fmaf(mv1.y, MASK_C, s[nt][3] * QK_SCALE);
        }

        // ---- online softmax ----
        float rm0 = s[0][0], rm1 = s[0][2];
#pragma unroll
        for (int nt = 0; nt < 8; nt++) {
            rm0 = fmaxf(rm0, fmaxf(s[nt][0], s[nt][1]));
            rm1 = fmaxf(rm1, fmaxf(s[nt][2], s[nt][3]));
        }
        rm0 = fmaxf(rm0, __shfl_xor_sync(0xffffffff, rm0, 1));
        rm0 = fmaxf(rm0, __shfl_xor_sync(0xffffffff, rm0, 2));
        rm1 = fmaxf(rm1, __shfl_xor_sync(0xffffffff, rm1, 1));
        rm1 = fmaxf(rm1, __shfl_xor_sync(0xffffffff, rm1, 2));

        float mn0 = fmaxf(m0r, rm0);
        float mn1 = fmaxf(m1r, rm1);
        float cr0 = ex2f(m0r - mn0);
        float cr1 = ex2f(m1r - mn1);
        m0r = mn0; m1r = mn1;

        float rs0 = 0.0f, rs1 = 0.0f;
#pragma unroll
        for (int nt = 0; nt < 8; nt++) {
            s[nt][0] = ex2f(s[nt][0] - mn0);
            s[nt][1] = ex2f(s[nt][1] - mn0);
            s[nt][2] = ex2f(s[nt][2] - mn1);
            s[nt][3] = ex2f(s[nt][3] - mn1);
            rs0 += s[nt][0] + s[nt][1];
            rs1 += s[nt][2] + s[nt][3];
        }
        rs0 += __shfl_xor_sync(0xffffffff, rs0, 1);
        rs0 += __shfl_xor_sync(0xffffffff, rs0, 2);
        rs1 += __shfl_xor_sync(0xffffffff, rs1, 1);
        rs1 += __shfl_xor_sync(0xffffffff, rs1, 2);
        l0r = l0r * cr0 + rs0;
        l1r = l1r * cr1 + rs1;

#pragma unroll
        for (int nt = 0; nt < 8; nt++) {
            o[nt][0] *= cr0; o[nt][1] *= cr0;
            o[nt][2] *= cr1; o[nt][3] *= cr1;
        }

        // ---- O += P @ V (hi/lo 3-term; P packed from registers) ----
#pragma unroll
        for (int k2 = 0; k2 < 4; k2++) {
            uint32_t ph[4], pl[4];
            split_pack_h(s[2 * k2][0],     s[2 * k2][1],     ph[0], pl[0]);
            split_pack_h(s[2 * k2][2],     s[2 * k2][3],     ph[1], pl[1]);
            split_pack_h(s[2 * k2 + 1][0], s[2 * k2 + 1][1], ph[2], pl[2]);
            split_pack_h(s[2 * k2 + 1][2], s[2 * k2 + 1][3], ph[3], pl[3]);
#pragma unroll
            for (int dt2 = 0; dt2 < 4; dt2++) {
                uint32_t va = stg + 2 * AKV_E * 2
                            + (uint32_t)((k2 * 16 + vfrow) * AP + dt2 * 16 + vfcol) * 2;
                uint32_t vh4[4], vl4[4];
                ldsm4t(vh4, va);
                ldsm4t(vl4, va + AKV_E * 2);
                mma16816(o[2 * dt2],     ph, vh4);
                mma16816(o[2 * dt2],     ph, vl4);
                mma16816(o[2 * dt2],     pl, vh4);
                mma16816(o[2 * dt2 + 1], ph, vh4 + 2);
                mma16816(o[2 * dt2 + 1], ph, vl4 + 2);
                mma16816(o[2 * dt2 + 1], pl, vh4 + 2);
            }
        }

        __syncthreads();
        if (c + 2 < NKV) issueKV(c + 2);
        CP_COMMIT();
    }

    // ---- epilogue: write ctx hi/lo fp16 ----
    const float inv0 = 1.0f / l0r;
    const float inv1 = 1.0f / l1r;
    const int r0 = q0 + warp * 16 + (lane >> 2);
    const size_t base0 = ((size_t)b * SEQ + r0) * EMB + h * HDIM + (lane & 3) * 2;
    const size_t base1 = base0 + 8 * EMB;
#pragma unroll
    for (int nt = 0; nt < 8; nt++) {
        uint32_t hh, ll;
        split_pack_h(o[nt][0] * inv0, o[nt][1] * inv0, hh, ll);
        ((uint32_t*)ctxh)[(base0 + nt * 8) >> 1] = hh;
        ((uint32_t*)ctxl)[(base0 + nt * 8) >> 1] = ll;
        split_pack_h(o[nt][2] * inv1, o[nt][3] * inv1, hh, ll);
        ((uint32_t*)ctxh)[(base1 + nt * 8) >> 1] = hh;
        ((uint32_t*)ctxl)[(base1 + nt * 8) >> 1] = ll;
    }
}

// ---------------------------------------------------------------------------
// Launch
// ---------------------------------------------------------------------------
extern "C" void kernel_launch(void* const* d_in, const int* in_sizes, int n_in,
                              void* d_out, int out_size)
{
    const float* x     = (const float*)d_in[0];
    const float* mask  = (const float*)d_in[1];
    const float* w_in  = (const float*)d_in[2];
    const float* b_in  = (const float*)d_in[3];
    const float* w_out = (const float*)d_in[4];
    const float* b_out = (const float*)d_in[5];
    float* out = (float*)d_out;

    void *pxh, *pxl, *pwih, *pwil, *pwoh, *pwol, *pqh, *pql, *pch, *pcl;
    cudaGetSymbolAddress(&pxh, g_xh);   cudaGetSymbolAddress(&pxl, g_xl);
    cudaGetSymbolAddress(&pwih, g_wih); cudaGetSymbolAddress(&pwil, g_wil);
    cudaGetSymbolAddress(&pwoh, g_woh); cudaGetSymbolAddress(&pwol, g_wol);
    cudaGetSymbolAddress(&pqh, g_qkvh); cudaGetSymbolAddress(&pql, g_qkvl);
    cudaGetSymbolAddress(&pch, g_ctxh); cudaGetSymbolAddress(&pcl, g_ctxl);

    cudaFuncSetAttribute(gemm_fp16hl, cudaFuncAttributeMaxDynamicSharedMemorySize, GEMM_SMEM);
    cudaFuncSetAttribute(attn_fp16, cudaFuncAttributeMaxDynamicSharedMemorySize, ATT_SMEM);

    // 0) preconvert x, W_in, W_out to fp16 hi/lo
    {
        int n4 = MROWS * EMB / 4;
        cvt_hl_kernel<<<(n4 + 255) / 256, 256>>>(x, (__half*)pxh, (__half*)pxl, n4);
        n4 = E3 * EMB / 4;
        cvt_hl_kernel<<<(n4 + 255) / 256, 256>>>(w_in, (__half*)pwih, (__half*)pwil, n4);
        n4 = EMB * EMB / 4;
        cvt_hl_kernel<<<(n4 + 255) / 256, 256>>>(w_out, (__half*)pwoh, (__half*)pwol, n4);
    }

    // 1) QKV projection -> qkv fp16 hi/lo
    {
        dim3 grid(E3 / 128, MROWS / 128);
        gemm_fp16hl<<<grid, 256, GEMM_SMEM>>>((__half*)pxh, (__half*)pxl,
                                              (__half*)pwih, (__half*)pwil,
                                              b_in, nullptr,
                                              (__half*)pqh, (__half*)pql,
                                              MROWS, E3, EMB);
    }

    // 2) attention -> ctx fp16 hi/lo
    {
        dim3 grid(SEQ / 128, HEADS, BATCH);
        attn_fp16<<<grid, 256, ATT_SMEM>>>((__half*)pqh, (__half*)pql, mask,
                                           (__half*)pch, (__half*)pcl);
    }

    // 3) output projection -> fp32 out
    {
        dim3 grid(EMB / 128, MROWS / 128);
        gemm_fp16hl<<<grid, 256, GEMM_SMEM>>>((__half*)pch, (__half*)pcl,
                                              (__half*)pwoh, (__half*)pwol,
                                              b_out, out, nullptr, nullptr,
                                              MROWS, EMB, EMB);
    }
}

// round 7
// speedup vs baseline: 1.5088x; 1.5088x over previous
#include <cuda_runtime.h>
#include <cuda_fp16.h>
#include <math.h>
#include <stdint.h>

// ---------------------------------------------------------------------------
// Problem constants
// ---------------------------------------------------------------------------
#define BATCH 2
#define SEQ   2048
#define EMB   1024
#define HEADS 16
#define HDIM  64
#define MROWS (BATCH * SEQ)        // 4096

__device__ float g_qkv[MROWS * 3 * EMB];   // [B*S, 3E]
__device__ float g_ctx[MROWS * EMB];       // [B*S, E]

// ---------------------------------------------------------------------------
// warp-MMA helpers (sm_80+ PTX — legal under compute_103; NO tcgen05)
// ---------------------------------------------------------------------------
__device__ __forceinline__ uint32_t smem_u32(const void* p) {
    uint32_t a;
    asm("{ .reg .u64 t; cvta.to.shared.u64 t, %1; cvt.u32.u64 %0, t; }"
        : "=r"(a) : "l"(p));
    return a;
}

__device__ __forceinline__ void ldsm4(uint32_t r[4], uint32_t addr) {
    asm volatile("ldmatrix.sync.aligned.m8n8.x4.shared.b16 {%0,%1,%2,%3}, [%4];"
                 : "=r"(r[0]), "=r"(r[1]), "=r"(r[2]), "=r"(r[3]) : "r"(addr));
}
__device__ __forceinline__ void ldsm4t(uint32_t r[4], uint32_t addr) {
    asm volatile("ldmatrix.sync.aligned.m8n8.x4.trans.shared.b16 {%0,%1,%2,%3}, [%4];"
                 : "=r"(r[0]), "=r"(r[1]), "=r"(r[2]), "=r"(r[3]) : "r"(addr));
}
__device__ __forceinline__ void ldsm2(uint32_t r[2], uint32_t addr) {
    asm volatile("ldmatrix.sync.aligned.m8n8.x2.shared.b16 {%0,%1}, [%2];"
                 : "=r"(r[0]), "=r"(r[1]) : "r"(addr));
}
__device__ __forceinline__ void mma16816(float d[4], const uint32_t a[4], const uint32_t b[2]) {
    asm volatile(
        "mma.sync.aligned.m16n8k16.row.col.f32.f16.f16.f32 "
        "{%0,%1,%2,%3}, {%4,%5,%6,%7}, {%8,%9}, {%0,%1,%2,%3};"
        : "+f"(d[0]), "+f"(d[1]), "+f"(d[2]), "+f"(d[3])
        : "r"(a[0]), "r"(a[1]), "r"(a[2]), "r"(a[3]), "r"(b[0]), "r"(b[1]));
}
__device__ __forceinline__ float ex2f(float x) {
    float y;
    asm("ex2.approx.f32 %0, %1;" : "=f"(y) : "f"(x));
    return y;
}

// split pair of floats into hi/lo fp16x2 words
__device__ __forceinline__ void split_pack_h(float a, float b, uint32_t& h, uint32_t& l) {
    __half2 hh = __float22half2_rn(make_float2(a, b));
    float2 f = __half22float2(hh);
    __half2 ll = __float22half2_rn(make_float2(a - f.x, b - f.y));
    h = *(uint32_t*)&hh;
    l = *(uint32_t*)&ll;
}

// ---------------------------------------------------------------------------
// GEMM NT, 2-term fp16 hi/lo: C[M,N] = (Ah+Al)[M,K] @ Bh[N,K]^T + bias[N]
// 128x128 CTA tile, 8 warps (2x4 of 64x32), K chunk 32, double-buffered smem,
// register-prefetch LDG pipeline, in-loop fp32->fp16 conversion.
// ---------------------------------------------------------------------------
#define PITCH 40                       // fp16 elems per smem row (80B)
#define TSZ   (128 * PITCH)            // elems per tile buffer (5120)
#define TSZB  (TSZ * 2)                // 10240 B
#define STAGEB (3 * TSZB)              // Ah,Al,Bh per stage = 30720 B
#define GSMEM  (2 * STAGEB)            // 61440 B

// A: store hi+lo
__device__ __forceinline__ void cvt_store8_hl(float4 v, __half* base, uint32_t off) {
    uint32_t h01, l01, h23, l23;
    split_pack_h(v.x, v.y, h01, l01);
    split_pack_h(v.z, v.w, h23, l23);
    uint2 hv = make_uint2(h01, h23);
    uint2 lv = make_uint2(l01, l23);
    *(uint2*)(base + off)       = hv;
    *(uint2*)(base + off + TSZ) = lv;
}
// B: hi only
__device__ __forceinline__ void cvt_store8_hi(float4 v, __half* base, uint32_t off) {
    __half2 h01 = __float22half2_rn(make_float2(v.x, v.y));
    __half2 h23 = __float22half2_rn(make_float2(v.z, v.w));
    uint2 hv;
    hv.x = *(uint32_t*)&h01; hv.y = *(uint32_t*)&h23;
    *(uint2*)(base + off) = hv;
}

__global__ void __launch_bounds__(256, 1)
gemm_mma_kernel(const float* __restrict__ A,
                const float* __restrict__ B,
                const float* __restrict__ bias,
                float* __restrict__ C,
                int M, int N, int K)
{
    extern __shared__ __half smem[];
    const uint32_t sb = smem_u32(smem);

    const int tid  = threadIdx.x;
    const int lane = tid & 31;
    const int warp = tid >> 5;
    const int wm   = warp & 1;
    const int wn   = warp >> 1;
    const int m0   = blockIdx.y * 128;
    const int n0   = blockIdx.x * 128;

    float acc[4][4][4];
#pragma unroll
    for (int mi = 0; mi < 4; mi++)
#pragma unroll
        for (int ni = 0; ni < 4; ni++)
#pragma unroll
            for (int f = 0; f < 4; f++) acc[mi][ni][f] = 0.0f;

    int lrow[4], lcol[4];
#pragma unroll
    for (int i = 0; i < 4; i++) {
        int idx = tid + i * 256;
        lrow[i] = idx >> 3;
        lcol[i] = (idx & 7) * 4;
    }

    const int nch = K / 32;
    float4 ra[4], rb[4];

#pragma unroll
    for (int i = 0; i < 4; i++) {
        ra[i] = *(const float4*)(A + (size_t)(m0 + lrow[i]) * K + lcol[i]);
        rb[i] = *(const float4*)(B + (size_t)(n0 + lrow[i]) * K + lcol[i]);
    }
    {
        __half* st = smem;   // stage 0
#pragma unroll
        for (int i = 0; i < 4; i++) {
            uint32_t off = lrow[i] * PITCH + lcol[i];
            cvt_store8_hl(ra[i], st, off);
            cvt_store8_hi(rb[i], st + 2 * TSZ, off);
        }
    }
    __syncthreads();

    const int arow  = lane & 15;
    const int acolb = (lane >> 4) * 8;
    const int brow  = lane & 7;
    const int bcolb = ((lane >> 3) & 1) * 8;

    for (int c = 0; c < nch; c++) {
        if (c + 1 < nch) {
            const float* Ap = A + (size_t)m0 * K + (c + 1) * 32;
            const float* Bp = B + (size_t)n0 * K + (c + 1) * 32;
#pragma unroll
            for (int i = 0; i < 4; i++) {
                ra[i] = *(const float4*)(Ap + (size_t)lrow[i] * K + lcol[i]);
                rb[i] = *(const float4*)(Bp + (size_t)lrow[i] * K + lcol[i]);
            }
        }

        const uint32_t stg = sb + (uint32_t)(c & 1) * STAGEB;
#pragma unroll
        for (int ks = 0; ks < 2; ks++) {
            uint32_t ah[4][4], al[4][4];
            const uint32_t acol = ks * 16 + acolb;
#pragma unroll
            for (int mi = 0; mi < 4; mi++) {
                uint32_t ad = stg + ((wm * 64 + mi * 16 + arow) * PITCH + acol) * 2;
                ldsm4(ah[mi], ad);
                ldsm4(al[mi], ad + TSZB);
            }
            const uint32_t bcol = ks * 16 + bcolb;
#pragma unroll
            for (int ni = 0; ni < 4; ni++) {
                uint32_t bd = stg + 2 * TSZB + ((wn * 32 + ni * 8 + brow) * PITCH + bcol) * 2;
                uint32_t bh[2];
                ldsm2(bh, bd);
#pragma unroll
                for (int mi = 0; mi < 4; mi++) {
                    mma16816(acc[mi][ni], ah[mi], bh);
                    mma16816(acc[mi][ni], al[mi], bh);
                }
            }
        }

        if (c + 1 < nch) {
            __half* st = smem + ((c + 1) & 1) * (STAGEB / 2);
#pragma unroll
            for (int i = 0; i < 4; i++) {
                uint32_t off = lrow[i] * PITCH + lcol[i];
                cvt_store8_hl(ra[i], st, off);
                cvt_store8_hi(rb[i], st + 2 * TSZ, off);
            }
            __syncthreads();
        }
    }

    const int erow = lane >> 2;
    const int ecol = (lane & 3) * 2;
#pragma unroll
    for (int mi = 0; mi < 4; mi++) {
        int r0 = m0 + wm * 64 + mi * 16 + erow;
#pragma unroll
        for (int ni = 0; ni < 4; ni++) {
            int cc = n0 + wn * 32 + ni * 8 + ecol;
            float b0 = bias[cc], b1 = bias[cc + 1];
            float2 v0 = make_float2(acc[mi][ni][0] + b0, acc[mi][ni][1] + b1);
            float2 v1 = make_float2(acc[mi][ni][2] + b0, acc[mi][ni][3] + b1);
            *(float2*)(C + (size_t)r0 * N + cc)       = v0;
            *(float2*)(C + (size_t)(r0 + 8) * N + cc) = v1;
        }
    }
}

// ---------------------------------------------------------------------------
// Flash attention, 2-term fp16 hi/lo:
//   S = (Qh+Ql) @ Kh^T,  O = (Ph+Pl) @ Vh
// CTA = 128 q x one (b,h). 8 warps x 16 q-rows. KV tiles of 64,
// double-buffered K/V (hi only) + register prefetch. Softmax log2 domain.
// ---------------------------------------------------------------------------
#define ABKV 64
#define APITCH 72                            // fp16 elems per smem row (144B)

// smem layout (fp16 elems)
#define Q_H   0
#define Q_L   (128 * APITCH)                 // 9216
#define KV0   (2 * 128 * APITCH)             // 18432; per stage:
#define VS_H  (64 * APITCH)                  // V hi after K hi
#define KVSTG (2 * 64 * APITCH)              // 9216 elems per stage
#define ASMEM ((KV0 + 2 * KVSTG) * 2)        // 73728 bytes

#define QK_SCALE (0.125f * 1.44269504089f)   // 1/sqrt(64) * log2(e)
#define MASK_C   (-14426.950408889634f)      // -10000 * log2(e)

__device__ __forceinline__ void cvt_split_store4(float4 v, __half* base,
                                                 uint32_t off_h, uint32_t off_l) {
    uint32_t h01, l01, h23, l23;
    split_pack_h(v.x, v.y, h01, l01);
    split_pack_h(v.z, v.w, h23, l23);
    *(uint2*)(base + off_h) = make_uint2(h01, h23);
    *(uint2*)(base + off_l) = make_uint2(l01, l23);
}
__device__ __forceinline__ void cvt_store4_hi(float4 v, __half* base, uint32_t off) {
    __half2 h01 = __float22half2_rn(make_float2(v.x, v.y));
    __half2 h23 = __float22half2_rn(make_float2(v.z, v.w));
    uint2 hv;
    hv.x = *(uint32_t*)&h01; hv.y = *(uint32_t*)&h23;
    *(uint2*)(base + off) = hv;
}

__global__ void __launch_bounds__(256, 1)
attn_mma_kernel(const float* __restrict__ qkv,
                const float* __restrict__ mask,
                float* __restrict__ ctx)
{
    extern __shared__ __half smem[];
    const uint32_t sb = smem_u32(smem);

    const int tid  = threadIdx.x;
    const int lane = tid & 31;
    const int warp = tid >> 5;
    const int qt = blockIdx.x;
    const int h  = blockIdx.y;
    const int b  = blockIdx.z;
    const int q0 = qt * 128;

    const size_t rowstride = 3 * EMB;
    const float* qbase = qkv + ((size_t)b * SEQ) * rowstride + h * HDIM;
    const float* kbase = qbase + EMB;
    const float* vbase = qbase + 2 * EMB;

    // ---- load Q (scaled), split hi/lo into smem ----
#pragma unroll
    for (int i = 0; i < 8; i++) {
        int idx = tid + i * 256;             // 0..2047
        int row = idx >> 4;                  // 0..127
        int c4  = (idx & 15) * 4;            // 0..60
        float4 v = *(const float4*)(qbase + (size_t)(q0 + row) * rowstride + c4);
        v.x *= QK_SCALE; v.y *= QK_SCALE; v.z *= QK_SCALE; v.w *= QK_SCALE;
        uint32_t off = row * APITCH + c4;
        cvt_split_store4(v, smem, Q_H + off, Q_L + off);
    }

    // ---- prologue: KV tile 0 ----
    int krow4[4], kcol4[4];
#pragma unroll
    for (int i = 0; i < 4; i++) {
        int idx = tid + i * 256;             // 0..1023
        krow4[i] = idx >> 4;                 // 0..63
        kcol4[i] = (idx & 15) * 4;
    }
    float4 rk[4], rv[4];
#pragma unroll
    for (int i = 0; i < 4; i++) {
        rk[i] = *(const float4*)(kbase + (size_t)krow4[i] * rowstride + kcol4[i]);
        rv[i] = *(const float4*)(vbase + (size_t)krow4[i] * rowstride + kcol4[i]);
    }
    {
        __half* st = smem + KV0;             // stage 0
#pragma unroll
        for (int i = 0; i < 4; i++) {
            uint32_t off = krow4[i] * APITCH + kcol4[i];
            cvt_store4_hi(rk[i], st, off);
            cvt_store4_hi(rv[i], st + VS_H, off);
        }
    }
    __syncthreads();

    // ---- Q fragments to registers (persistent) ----
    uint32_t qh[4][4], ql[4][4];
    {
        const int arow  = warp * 16 + (lane & 15);
        const int acolb = (lane >> 4) * 8;
#pragma unroll
        for (int ks = 0; ks < 4; ks++) {
            uint32_t ad = sb + (uint32_t)(arow * APITCH + ks * 16 + acolb) * 2;
            ldsm4(qh[ks], ad);
            ldsm4(ql[ks], ad + Q_L * 2);
        }
    }

    // ---- state ----
    float o[8][4];
#pragma unroll
    for (int nt = 0; nt < 8; nt++)
#pragma unroll
        for (int f = 0; f < 4; f++) o[nt][f] = 0.0f;
    float m0r = -INFINITY, m1r = -INFINITY;
    float l0r = 0.0f, l1r = 0.0f;

    const int kfrow = ((lane >> 4) & 1) * 8 + (lane & 7);
    const int kfcol = ((lane >> 3) & 1) * 8;
    const int vfrow = ((lane >> 3) & 1) * 8 + (lane & 7);
    const int vfcol = ((lane >> 4) & 1) * 8;
    const float* mrow0 = mask + ((size_t)b * SEQ + q0 + warp * 16 + (lane >> 2)) * SEQ
                         + (lane & 3) * 2;
    const float* mrow1 = mrow0 + 8 * SEQ;

    const int NKV = SEQ / ABKV;              // 32
#pragma unroll 1
    for (int c = 0; c < NKV; c++) {
        // prefetch next tile
        if (c + 1 < NKV) {
            const float* kp = kbase + (size_t)(c + 1) * ABKV * rowstride;
            const float* vp = vbase + (size_t)(c + 1) * ABKV * rowstride;
#pragma unroll
            for (int i = 0; i < 4; i++) {
                rk[i] = *(const float4*)(kp + (size_t)krow4[i] * rowstride + kcol4[i]);
                rv[i] = *(const float4*)(vp + (size_t)krow4[i] * rowstride + kcol4[i]);
            }
        }

        const uint32_t stg = sb + (uint32_t)(KV0 + (c & 1) * KVSTG) * 2;

        // ---- S = (Qh+Ql) @ Kh^T ----
        float s[8][4];
#pragma unroll
        for (int nt = 0; nt < 8; nt++)
#pragma unroll
            for (int f = 0; f < 4; f++) s[nt][f] = 0.0f;

#pragma unroll
        for (int ks = 0; ks < 4; ks++) {
#pragma unroll
            for (int nt2 = 0; nt2 < 4; nt2++) {
                uint32_t ka = stg + (uint32_t)((nt2 * 16 + kfrow) * APITCH + ks * 16 + kfcol) * 2;
                uint32_t kh4[4];
                ldsm4(kh4, ka);
                mma16816(s[2 * nt2],     qh[ks], kh4);
                mma16816(s[2 * nt2],     ql[ks], kh4);
                mma16816(s[2 * nt2 + 1], qh[ks], kh4 + 2);
                mma16816(s[2 * nt2 + 1], ql[ks], kh4 + 2);
            }
        }

        // ---- mask ----
        const int kvb = c * ABKV;
#pragma unroll
        for (int nt = 0; nt < 8; nt++) {
            float2 mv0 = *(const float2*)(mrow0 + kvb + nt * 8);
            float2 mv1 = *(const float2*)(mrow1 + kvb + nt * 8);
            s[nt][0] = fmaf(mv0.x, MASK_C, s[nt][0]);
            s[nt][1] = fmaf(mv0.y, MASK_C, s[nt][1]);
            s[nt][2] = fmaf(mv1.x, MASK_C, s[nt][2]);
            s[nt][3] = fmaf(mv1.y, MASK_C, s[nt][3]);
        }

        // ---- online softmax (log2 domain) ----
        float rm0 = s[0][0], rm1 = s[0][2];
#pragma unroll
        for (int nt = 0; nt < 8; nt++) {
            rm0 = fmaxf(rm0, fmaxf(s[nt][0], s[nt][1]));
            rm1 = fmaxf(rm1, fmaxf(s[nt][2], s[nt][3]));
        }
        rm0 = fmaxf(rm0, __shfl_xor_sync(0xffffffff, rm0, 1));
        rm0 = fmaxf(rm0, __shfl_xor_sync(0xffffffff, rm0, 2));
        rm1 = fmaxf(rm1, __shfl_xor_sync(0xffffffff, rm1, 1));
        rm1 = fmaxf(rm1, __shfl_xor_sync(0xffffffff, rm1, 2));

        float mn0 = fmaxf(m0r, rm0);
        float mn1 = fmaxf(m1r, rm1);
        float cr0 = ex2f(m0r - mn0);
        float cr1 = ex2f(m1r - mn1);
        m0r = mn0; m1r = mn1;

        float rs0 = 0.0f, rs1 = 0.0f;
#pragma unroll
        for (int nt = 0; nt < 8; nt++) {
            s[nt][0] = ex2f(s[nt][0] - mn0);
            s[nt][1] = ex2f(s[nt][1] - mn0);
            s[nt][2] = ex2f(s[nt][2] - mn1);
            s[nt][3] = ex2f(s[nt][3] - mn1);
            rs0 += s[nt][0] + s[nt][1];
            rs1 += s[nt][2] + s[nt][3];
        }
        rs0 += __shfl_xor_sync(0xffffffff, rs0, 1);
        rs0 += __shfl_xor_sync(0xffffffff, rs0, 2);
        rs1 += __shfl_xor_sync(0xffffffff, rs1, 1);
        rs1 += __shfl_xor_sync(0xffffffff, rs1, 2);
        l0r = l0r * cr0 + rs0;
        l1r = l1r * cr1 + rs1;

#pragma unroll
        for (int nt = 0; nt < 8; nt++) {
            o[nt][0] *= cr0; o[nt][1] *= cr0;
            o[nt][2] *= cr1; o[nt][3] *= cr1;
        }

        // ---- O += (Ph+Pl) @ Vh ----
#pragma unroll
        for (int k2 = 0; k2 < 4; k2++) {
            uint32_t ph[4], pl[4];
            split_pack_h(s[2 * k2][0],     s[2 * k2][1],     ph[0], pl[0]);
            split_pack_h(s[2 * k2][2],     s[2 * k2][3],     ph[1], pl[1]);
            split_pack_h(s[2 * k2 + 1][0], s[2 * k2 + 1][1], ph[2], pl[2]);
            split_pack_h(s[2 * k2 + 1][2], s[2 * k2 + 1][3], ph[3], pl[3]);
#pragma unroll
            for (int dt2 = 0; dt2 < 4; dt2++) {
                uint32_t va = stg + (uint32_t)(VS_H + (k2 * 16 + vfrow) * APITCH
                                               + dt2 * 16 + vfcol) * 2;
                uint32_t vh4[4];
                ldsm4t(vh4, va);
                mma16816(o[2 * dt2],     ph, vh4);
                mma16816(o[2 * dt2],     pl, vh4);
                mma16816(o[2 * dt2 + 1], ph, vh4 + 2);
                mma16816(o[2 * dt2 + 1], pl, vh4 + 2);
            }
        }

        // ---- store next tile (other stage) ----
        if (c + 1 < NKV) {
            __half* st = smem + KV0 + ((c + 1) & 1) * KVSTG;
#pragma unroll
            for (int i = 0; i < 4; i++) {
                uint32_t off = krow4[i] * APITCH + kcol4[i];
                cvt_store4_hi(rk[i], st, off);
                cvt_store4_hi(rv[i], st + VS_H, off);
            }
            __syncthreads();
        }
    }

    // ---- epilogue ----
    const float inv0 = 1.0f / l0r;
    const float inv1 = 1.0f / l1r;
    const int r0 = q0 + warp * 16 + (lane >> 2);
    float* crow0 = ctx + ((size_t)b * SEQ + r0) * EMB + h * HDIM + (lane & 3) * 2;
    float* crow1 = crow0 + 8 * EMB;
#pragma unroll
    for (int nt = 0; nt < 8; nt++) {
        *(float2*)(crow0 + nt * 8) = make_float2(o[nt][0] * inv0, o[nt][1] * inv0);
        *(float2*)(crow1 + nt * 8) = make_float2(o[nt][2] * inv1, o[nt][3] * inv1);
    }
}

// ---------------------------------------------------------------------------
// Launch
// ---------------------------------------------------------------------------
extern "C" void kernel_launch(void* const* d_in, const int* in_sizes, int n_in,
                              void* d_out, int out_size)
{
    const float* x     = (const float*)d_in[0];
    const float* mask  = (const float*)d_in[1];
    const float* w_in  = (const float*)d_in[2];
    const float* b_in  = (const float*)d_in[3];
    const float* w_out = (const float*)d_in[4];
    const float* b_out = (const float*)d_in[5];
    float* out = (float*)d_out;

    void* pq = nullptr;
    void* pc = nullptr;
    cudaGetSymbolAddress(&pq, g_qkv);
    cudaGetSymbolAddress(&pc, g_ctx);
    float* qkv = (float*)pq;
    float* ctx = (float*)pc;

    cudaFuncSetAttribute(gemm_mma_kernel, cudaFuncAttributeMaxDynamicSharedMemorySize, GSMEM);
    cudaFuncSetAttribute(attn_mma_kernel, cudaFuncAttributeMaxDynamicSharedMemorySize, ASMEM);

    // 1) QKV projection
    {
        dim3 grid(3 * EMB / 128, MROWS / 128);
        gemm_mma_kernel<<<grid, 256, GSMEM>>>(x, w_in, b_in, qkv, MROWS, 3 * EMB, EMB);
    }

    // 2) attention -> ctx [B,S,E]
    {
        dim3 grid(SEQ / 128, HEADS, BATCH);
        attn_mma_kernel<<<grid, 256, ASMEM>>>(qkv, mask, ctx);
    }

    // 3) output projection
    {
        dim3 grid(EMB / 128, MROWS / 128);
        gemm_mma_kernel<<<grid, 256, GSMEM>>>(ctx, w_out, b_out, out, MROWS, EMB, EMB);
    }
}